// round 14
// baseline (speedup 1.0000x reference)
#include <cuda_runtime.h>
#include <cuda_bf16.h>
#include <math.h>
#include <stdint.h>

namespace {
constexpr int kH  = 2048;
constexpr int kNH = 16;
constexpr int kD  = 128;
constexpr int kB  = 2;
constexpr int kS  = 2048;
constexpr int kM  = kB * kS;          // 4096
constexpr int kNumChunks = kH / 64;   // 32
constexpr int kStageBytes = 98304;    // Ahi 16K | Alo 16K | Bhi 32K | Blo 32K
constexpr int kDynSmem = 2 * kStageBytes + 1024;
constexpr int kTilesPerGemm = (kM / 128) * (kH / 256);   // 256
constexpr int kGemmGrid = 148;
}

// ---------------- scratch ----------------
__device__ float g_qraw[(size_t)kM * kH];
__device__ float g_kraw[(size_t)kM * kH];
__device__ float g_vraw[(size_t)kM * kH];
__device__ float g_graw[(size_t)kM * kH];
__device__ float g_qact[(size_t)kM * kH];
__device__ float g_kact[(size_t)kM * kH];
__device__ float g_vact[(size_t)kM * kH];
__device__ float g_obuf[(size_t)kM * kH];
__device__ float g_alpha[(size_t)kM * kNH];
__device__ float g_beta[(size_t)kM * kNH];
__device__ __nv_bfloat16 g_xhi[(size_t)kM * kH];
__device__ __nv_bfloat16 g_xlo[(size_t)kM * kH];
__device__ __nv_bfloat16 g_ghi[(size_t)kM * kH];
__device__ __nv_bfloat16 g_glo[(size_t)kM * kH];
__device__ __nv_bfloat16 g_wqhi[(size_t)kH * kH];
__device__ __nv_bfloat16 g_wqlo[(size_t)kH * kH];
__device__ __nv_bfloat16 g_wkhi[(size_t)kH * kH];
__device__ __nv_bfloat16 g_wklo[(size_t)kH * kH];
__device__ __nv_bfloat16 g_wvhi[(size_t)kH * kH];
__device__ __nv_bfloat16 g_wvlo[(size_t)kH * kH];
__device__ __nv_bfloat16 g_wghi[(size_t)kH * kH];
__device__ __nv_bfloat16 g_wglo[(size_t)kH * kH];
__device__ __nv_bfloat16 g_wohi[(size_t)kH * kH];
__device__ __nv_bfloat16 g_wolo[(size_t)kH * kH];

// ---------------- helpers ----------------
__device__ __forceinline__ uint32_t smem_u32(const void* p) {
  uint32_t a;
  asm("{ .reg .u64 t; cvta.to.shared.u64 t, %1; cvt.u32.u64 %0, t; }" : "=r"(a) : "l"(p));
  return a;
}
__device__ __forceinline__ void cp16(uint32_t dst, const void* src) {
  asm volatile("cp.async.cg.shared.global [%0], [%1], 16;" :: "r"(dst), "l"(src));
}
__device__ __forceinline__ void ldsm_x4(uint32_t* r, uint32_t addr) {
  asm volatile("ldmatrix.sync.aligned.m8n8.x4.shared.b16 {%0,%1,%2,%3}, [%4];"
               : "=r"(r[0]), "=r"(r[1]), "=r"(r[2]), "=r"(r[3]) : "r"(addr));
}
__device__ __forceinline__ void mma_bf16(float* d, const uint32_t* a, const uint32_t* b) {
  asm volatile("mma.sync.aligned.m16n8k16.row.col.f32.bf16.bf16.f32 "
               "{%0,%1,%2,%3}, {%4,%5,%6,%7}, {%8,%9}, {%0,%1,%2,%3};"
               : "+f"(d[0]), "+f"(d[1]), "+f"(d[2]), "+f"(d[3])
               : "r"(a[0]), "r"(a[1]), "r"(a[2]), "r"(a[3]), "r"(b[0]), "r"(b[1]));
}

// ---------------- bf16 split (rows) ----------------
__global__ __launch_bounds__(256) void split_rows(const float4* __restrict__ in,
                                                  __nv_bfloat162* __restrict__ hi,
                                                  __nv_bfloat162* __restrict__ lo,
                                                  int n4) {
  int i = blockIdx.x * 256 + threadIdx.x;
  if (i >= n4) return;
  float4 v = in[i];
  __nv_bfloat162 h01, h23, l01, l23;
  h01.x = __float2bfloat16_rn(v.x);
  h01.y = __float2bfloat16_rn(v.y);
  h23.x = __float2bfloat16_rn(v.z);
  h23.y = __float2bfloat16_rn(v.w);
  l01.x = __float2bfloat16_rn(v.x - __bfloat162float(h01.x));
  l01.y = __float2bfloat16_rn(v.y - __bfloat162float(h01.y));
  l23.x = __float2bfloat16_rn(v.z - __bfloat162float(h23.x));
  l23.y = __float2bfloat16_rn(v.w - __bfloat162float(h23.y));
  hi[2 * i] = h01; hi[2 * i + 1] = h23;
  lo[2 * i] = l01; lo[2 * i + 1] = l23;
}

// ---------------- fused bf16 split + transpose for 5 weights ----------------
// blockIdx.z selects which W; Wt[N,K] layout.
__global__ __launch_bounds__(256) void split_T5(const float* __restrict__ W0,
                                                const float* __restrict__ W1,
                                                const float* __restrict__ W2,
                                                const float* __restrict__ W3,
                                                const float* __restrict__ W4,
                                                __nv_bfloat16* __restrict__ T0h, __nv_bfloat16* __restrict__ T0l,
                                                __nv_bfloat16* __restrict__ T1h, __nv_bfloat16* __restrict__ T1l,
                                                __nv_bfloat16* __restrict__ T2h, __nv_bfloat16* __restrict__ T2l,
                                                __nv_bfloat16* __restrict__ T3h, __nv_bfloat16* __restrict__ T3l,
                                                __nv_bfloat16* __restrict__ T4h, __nv_bfloat16* __restrict__ T4l) {
  __shared__ float t[32][33];
  const int z = blockIdx.z;
  const float* W = (z == 0) ? W0 : (z == 1) ? W1 : (z == 2) ? W2 : (z == 3) ? W3 : W4;
  __nv_bfloat16* Thi = (z == 0) ? T0h : (z == 1) ? T1h : (z == 2) ? T2h : (z == 3) ? T3h : T4h;
  __nv_bfloat16* Tlo = (z == 0) ? T0l : (z == 1) ? T1l : (z == 2) ? T2l : (z == 3) ? T3l : T4l;
  const int n0 = blockIdx.x * 32, k0 = blockIdx.y * 32;
  const int tx = threadIdx.x & 31, ty = threadIdx.x >> 5;
#pragma unroll
  for (int r = ty; r < 32; r += 8) t[r][tx] = W[(size_t)(k0 + r) * kH + n0 + tx];
  __syncthreads();
#pragma unroll
  for (int r = ty; r < 32; r += 8) {
    float v = t[tx][r];
    __nv_bfloat16 h = __float2bfloat16_rn(v);
    __nv_bfloat16 l = __float2bfloat16_rn(v - __bfloat162float(h));
    size_t o = (size_t)(n0 + r) * kH + k0 + tx;
    Thi[o] = h;
    Tlo[o] = l;
  }
}

// ---------------- persistent HMMA bf16x3 GEMM, 128x256 tile, 2-stage -------
__global__ __launch_bounds__(256, 1)
void gemm_bf16x3_persist(const __nv_bfloat16* __restrict__ Ahi,
                         const __nv_bfloat16* __restrict__ Alo,
                         const __nv_bfloat16* __restrict__ B0h, const __nv_bfloat16* __restrict__ B0l, float* __restrict__ C0,
                         const __nv_bfloat16* __restrict__ B1h, const __nv_bfloat16* __restrict__ B1l, float* __restrict__ C1,
                         const __nv_bfloat16* __restrict__ B2h, const __nv_bfloat16* __restrict__ B2l, float* __restrict__ C2,
                         const __nv_bfloat16* __restrict__ B3h, const __nv_bfloat16* __restrict__ B3l, float* __restrict__ C3,
                         int totalTiles) {
  extern __shared__ char dsm[];
  const __nv_bfloat16* Bh[4] = {B0h, B1h, B2h, B3h};
  const __nv_bfloat16* Bl[4] = {B0l, B1l, B2l, B3l};
  float* Cp[4] = {C0, C1, C2, C3};

  const int tid = threadIdx.x;
  const int wid = tid >> 5;
  const int lane = tid & 31;
  const int wm = (wid & 1) * 64;      // warp tile 64x64, grid 2(m) x 4(n)
  const int wn = (wid >> 1) * 64;
  const uint32_t s0 = (smem_u32(dsm) + 1023u) & ~1023u;

  int ltile = blockIdx.x;
  int lck = 0;
  auto load_chunk = [&](int buf) {
    if (ltile < totalTiles) {
      const int w = ltile >> 8;
      const int ll = ltile & 255;
      const int lbm = (ll >> 3) << 7;
      const int lbn = (ll & 7) << 8;
      const uint32_t sb = s0 + buf * kStageBytes;
      {
        const __nv_bfloat16* srcs[2] = {Ahi, Alo};
#pragma unroll
        for (int tA = 0; tA < 2; ++tA) {
          const uint32_t db = sb + tA * 16384;
          const __nv_bfloat16* src = srcs[tA];
#pragma unroll
          for (int r = 0; r < 4; ++r) {
            int g = tid + r * 256;
            int m = g >> 3, j = g & 7;
            uint32_t dst = db + m * 128 + ((j ^ (m & 7)) << 4);
            cp16(dst, src + (size_t)(lbm + m) * kH + lck * 64 + j * 8);
          }
        }
      }
      {
        const __nv_bfloat16* srcs[2] = {Bh[w], Bl[w]};
#pragma unroll
        for (int tB = 0; tB < 2; ++tB) {
          const uint32_t db = sb + 32768 + tB * 32768;
          const __nv_bfloat16* src = srcs[tB];
#pragma unroll
          for (int r = 0; r < 8; ++r) {
            int g = tid + r * 256;
            int m = g >> 3, j = g & 7;
            uint32_t dst = db + m * 128 + ((j ^ (m & 7)) << 4);
            cp16(dst, src + (size_t)(lbn + m) * kH + lck * 64 + j * 8);
          }
        }
      }
    }
    asm volatile("cp.async.commit_group;");
    if (++lck == kNumChunks) { lck = 0; ltile += kGemmGrid; }
  };

  load_chunk(0);
  load_chunk(1);
  int cbuf = 0;

  for (int ctile = blockIdx.x; ctile < totalTiles; ctile += kGemmGrid) {
    const int which = ctile >> 8;
    const int loc = ctile & 255;
    const int bm = (loc >> 3) << 7;
    const int bn = (loc & 7) << 8;

    float acc[4][8][4];
#pragma unroll
    for (int i = 0; i < 4; ++i)
#pragma unroll
      for (int j = 0; j < 8; ++j)
#pragma unroll
        for (int kq = 0; kq < 4; ++kq) acc[i][j][kq] = 0.f;

    for (int ck = 0; ck < kNumChunks; ++ck) {
      asm volatile("cp.async.wait_group 1;" ::: "memory");
      __syncthreads();

      const uint32_t aHi = s0 + cbuf * kStageBytes;
      const uint32_t aLo = aHi + 16384;
      const uint32_t bHi = aHi + 32768;
      const uint32_t bLo = aHi + 65536;

      const int amRow = wm + (lane & 15);
      const int bnRowP = wn + (lane & 7) + ((lane >> 4) & 1) * 8;

#pragma unroll
      for (int ks = 0; ks < 4; ++ks) {
        const int kcA = ks * 2 + (lane >> 4);
        const int kcB = ks * 2 + ((lane >> 3) & 1);
        uint32_t bh[4][4], bl[4][4];
#pragma unroll
        for (int np = 0; np < 4; ++np) {
          int n = bnRowP + np * 16;
          uint32_t off = n * 128 + ((kcB ^ (n & 7)) << 4);
          ldsm_x4(bh[np], bHi + off);
          ldsm_x4(bl[np], bLo + off);
        }
#pragma unroll
        for (int mt = 0; mt < 4; ++mt) {
          uint32_t ah[4], al[4];
          int m = amRow + mt * 16;
          uint32_t off = m * 128 + ((kcA ^ (m & 7)) << 4);
          ldsm_x4(ah, aHi + off);
          ldsm_x4(al, aLo + off);
#pragma unroll
          for (int nt = 0; nt < 8; ++nt) {
            const uint32_t* bhp = &bh[nt >> 1][(nt & 1) * 2];
            const uint32_t* blp = &bl[nt >> 1][(nt & 1) * 2];
            mma_bf16(acc[mt][nt], ah, bhp);
            mma_bf16(acc[mt][nt], ah, blp);
            mma_bf16(acc[mt][nt], al, bhp);
          }
        }
      }
      __syncthreads();
      load_chunk(cbuf);
      cbuf ^= 1;
    }

    float* C = Cp[which];
    const int r0 = lane >> 2;
    const int c0 = (lane & 3) * 2;
#pragma unroll
    for (int mt = 0; mt < 4; ++mt) {
#pragma unroll
      for (int nt = 0; nt < 8; ++nt) {
        float* p0 = C + (size_t)(bm + wm + mt * 16 + r0) * kH + bn + wn + nt * 8 + c0;
        float* p1 = p0 + 8 * kH;
        *(float2*)p0 = make_float2(acc[mt][nt][0], acc[mt][nt][1]);
        *(float2*)p1 = make_float2(acc[mt][nt][2], acc[mt][nt][3]);
      }
    }
  }
}

// ---------------- fused causal depthwise conv (K=4) + SiLU for q,k,v -------
__global__ __launch_bounds__(256) void conv_silu3(const float* __restrict__ qin,
                                                  const float* __restrict__ kin,
                                                  const float* __restrict__ vin,
                                                  const float* __restrict__ qw, const float* __restrict__ qbias,
                                                  const float* __restrict__ kw, const float* __restrict__ kbias,
                                                  const float* __restrict__ vw, const float* __restrict__ vbias,
                                                  float* __restrict__ qout,
                                                  float* __restrict__ kout,
                                                  float* __restrict__ vout) {
  const int which = blockIdx.y;
  const float* in   = (which == 0) ? qin : (which == 1) ? kin : vin;
  const float* w    = (which == 0) ? qw : (which == 1) ? kw : vw;
  const float* bias = (which == 0) ? qbias : (which == 1) ? kbias : vbias;
  float* out        = (which == 0) ? qout : (which == 1) ? kout : vout;
  const float scale = (which == 1) ? 0.08838834764831845f : 1.f;

  int idx = blockIdx.x * 256 + threadIdx.x;
  int c  = idx & (kH - 1);
  int sb = idx >> 11;
  int s  = sb & (kS - 1);
  const float w0 = w[c * 4 + 0], w1 = w[c * 4 + 1], w2 = w[c * 4 + 2], w3 = w[c * 4 + 3];
  const float* p = in + (size_t)sb * kH + c;
  float y = bias[c] + w3 * p[0];
  if (s >= 1) y += w2 * p[-(ptrdiff_t)kH];
  if (s >= 2) y += w1 * p[-(ptrdiff_t)(2 * kH)];
  if (s >= 3) y += w0 * p[-(ptrdiff_t)(3 * kH)];
  float sg = 1.f / (1.f + __expf(-y));
  out[idx] = y * sg * scale;
}

// ---------------- alpha/beta ----------------
__global__ __launch_bounds__(256) void ab_proj(const float* __restrict__ x,
                                               const float* __restrict__ Wa,
                                               const float* __restrict__ ba,
                                               const float* __restrict__ Wb,
                                               const float* __restrict__ bb,
                                               float* __restrict__ alpha,
                                               float* __restrict__ beta) {
  __shared__ float xs[kH];
  const int row = blockIdx.x;
  const int t = threadIdx.x;
  const float* xr = x + (size_t)row * kH;
#pragma unroll
  for (int i = 0; i < kH / 256; ++i) xs[t + i * 256] = xr[t + i * 256];
  __syncthreads();
  const int g = t >> 3;
  const int l = t & 7;
  const int head = g & 15;
  const float* W = (g < 16) ? Wa : Wb;
  float acc = 0.f;
  for (int kk = l; kk < kH; kk += 8) acc = fmaf(xs[kk], W[kk * kNH + head], acc);
  acc += __shfl_xor_sync(0xffffffffu, acc, 1);
  acc += __shfl_xor_sync(0xffffffffu, acc, 2);
  acc += __shfl_xor_sync(0xffffffffu, acc, 4);
  if (l == 0) {
    float bias = (g < 16) ? ba[head] : bb[head];
    float v = 1.f / (1.f + __expf(-(acc + bias)));
    if (g < 16) alpha[(size_t)row * kNH + head] = v;
    else        beta [(size_t)row * kNH + head] = v;
  }
}

// ---------------- delta-rule recurrence: warp-independent -------------------
#define CPA4(dst, src) asm volatile("cp.async.ca.shared.global [%0], [%1], 4;" :: "r"(dst), "l"(src))

__global__ __launch_bounds__(128) void recurrence(const float* __restrict__ qb,
                                                  const float* __restrict__ kb,
                                                  const float* __restrict__ vb,
                                                  const float* __restrict__ alpha,
                                                  const float* __restrict__ beta,
                                                  float* __restrict__ ob) {
  __shared__ __align__(16) float s_k[4][4][128];   // [warp][buf][col]
  __shared__ __align__(16) float s_q[4][4][128];
  __shared__ __align__(16) float s_v[4][4][8];
  __shared__ float s_ab[4][4][2];

  const int t = threadIdx.x;
  const int w = t >> 5;
  const int lane = t & 31;
  const int bid = blockIdx.x;
  const int chunk = bid & 3;
  const int bh = bid >> 2;
  const int h = bh & 15;
  const int b = bh >> 4;
  const size_t head_off = (size_t)h * kD;
  const size_t bs_base = (size_t)b * kS;
  const int rowbase = chunk * 32 + w * 8;

  float S[32];
#pragma unroll
  for (int i = 0; i < 32; ++i) S[i] = 0.f;

  const int r = lane >> 2;
  const int qtr = lane & 3;

  auto issue = [&](int s, int buf) {
    size_t off = (bs_base + s) * (size_t)kH + head_off;
    uint32_t a;
    a = (uint32_t)__cvta_generic_to_shared(&s_k[w][buf][lane * 4]);
    cp16(a, kb + off + lane * 4);
    a = (uint32_t)__cvta_generic_to_shared(&s_q[w][buf][lane * 4]);
    cp16(a, qb + off + lane * 4);
    if (lane < 2) {
      a = (uint32_t)__cvta_generic_to_shared(&s_v[w][buf][lane * 4]);
      cp16(a, vb + off + rowbase + lane * 4);
    } else if (lane == 2) {
      a = (uint32_t)__cvta_generic_to_shared(&s_ab[w][buf][0]);
      CPA4(a, alpha + (bs_base + s) * kNH + h);
    } else if (lane == 3) {
      a = (uint32_t)__cvta_generic_to_shared(&s_ab[w][buf][1]);
      CPA4(a, beta + (bs_base + s) * kNH + h);
    }
    asm volatile("cp.async.commit_group;");
  };

  issue(0, 0);
  issue(1, 1);
  issue(2, 2);

#pragma unroll 2
  for (int s = 0; s < kS; ++s) {
    int pf = s + 3;
    if (pf > kS - 1) pf = kS - 1;
    issue(pf, (s + 3) & 3);
    asm volatile("cp.async.wait_group 3;");
    __syncwarp();

    const int buf = s & 3;
    const float4* kp = (const float4*)&s_k[w][buf][qtr * 32];
    const float4* qp = (const float4*)&s_q[w][buf][qtr * 32];
    const float a_ = s_ab[w][buf][0];
    const float b_ = s_ab[w][buf][1];
    const float vi = s_v[w][buf][r];

    float4 kr[8];
    float d0 = 0.f, d1 = 0.f, d2 = 0.f, d3 = 0.f;
#pragma unroll
    for (int m = 0; m < 8; ++m) {
      kr[m] = kp[m];
      d0 = fmaf(S[4 * m + 0], kr[m].x, d0);
      d1 = fmaf(S[4 * m + 1], kr[m].y, d1);
      d2 = fmaf(S[4 * m + 2], kr[m].z, d2);
      d3 = fmaf(S[4 * m + 3], kr[m].w, d3);
    }
    float sk = (d0 + d1) + (d2 + d3);
    sk += __shfl_xor_sync(0xffffffffu, sk, 1);
    sk += __shfl_xor_sync(0xffffffffu, sk, 2);
    const float c = -b_ * (sk - vi);

    float o0 = 0.f, o1 = 0.f, o2 = 0.f, o3 = 0.f;
#pragma unroll
    for (int m = 0; m < 8; ++m) {
      float4 qv = qp[m];
      S[4 * m + 0] = fmaf(c, kr[m].x, a_ * S[4 * m + 0]);
      S[4 * m + 1] = fmaf(c, kr[m].y, a_ * S[4 * m + 1]);
      S[4 * m + 2] = fmaf(c, kr[m].z, a_ * S[4 * m + 2]);
      S[4 * m + 3] = fmaf(c, kr[m].w, a_ * S[4 * m + 3]);
      o0 = fmaf(S[4 * m + 0], qv.x, o0);
      o1 = fmaf(S[4 * m + 1], qv.y, o1);
      o2 = fmaf(S[4 * m + 2], qv.z, o2);
      o3 = fmaf(S[4 * m + 3], qv.w, o3);
    }
    float oo = (o0 + o1) + (o2 + o3);
    oo += __shfl_xor_sync(0xffffffffu, oo, 1);
    oo += __shfl_xor_sync(0xffffffffu, oo, 2);
    if (qtr == 0) {
      ob[(bs_base + s) * (size_t)kH + head_off + rowbase + r] = oo;
    }
    // no trailing __syncwarp: the o-reduce shfl.sync above already converges
    // all lanes past their last smem reads of this buffer; next overwrite of
    // this buffer is 4 steps away.
  }
}

// ---------------- LayerNorm + gate + bf16 split (fused) ---------------------
__global__ __launch_bounds__(128) void ln_gate_split(const float* __restrict__ ob,
                                                     const float* __restrict__ graw,
                                                     const float* __restrict__ lnw,
                                                     const float* __restrict__ lnb,
                                                     __nv_bfloat16* __restrict__ ghi,
                                                     __nv_bfloat16* __restrict__ glo) {
  __shared__ float red[8];
  const int bs = blockIdx.x;
  const int h = blockIdx.y;
  const int t = threadIdx.x;
  size_t idx = (size_t)bs * kH + (size_t)h * kD + t;
  float v = ob[idx];
  float s1 = v, s2 = v * v;
#pragma unroll
  for (int w = 16; w; w >>= 1) {
    s1 += __shfl_xor_sync(0xffffffffu, s1, w);
    s2 += __shfl_xor_sync(0xffffffffu, s2, w);
  }
  const int wid = t >> 5, lane = t & 31;
  if (lane == 0) { red[wid] = s1; red[4 + wid] = s2; }
  __syncthreads();
  if (t == 0) {
    red[0] = red[0] + red[1] + red[2] + red[3];
    red[4] = red[4] + red[5] + red[6] + red[7];
  }
  __syncthreads();
  float mean = red[0] * (1.f / 128.f);
  float var = red[4] * (1.f / 128.f) - mean * mean;
  float rs = rsqrtf(var + 1e-5f);
  float y = (v - mean) * rs * lnw[t] + lnb[t];
  float gv = graw[idx];
  float o = y * (1.f / (1.f + __expf(-gv)));
  __nv_bfloat16 hi = __float2bfloat16_rn(o);
  __nv_bfloat16 lo = __float2bfloat16_rn(o - __bfloat162float(hi));
  ghi[idx] = hi;
  glo[idx] = lo;
}

// ---------------- launcher ----------------
extern "C" void kernel_launch(void* const* d_in, const int* in_sizes, int n_in,
                              void* d_out, int out_size) {
  const float* x   = (const float*)d_in[0];
  const float* Wq  = (const float*)d_in[1];
  const float* Wk  = (const float*)d_in[2];
  const float* Wv  = (const float*)d_in[3];
  const float* Wa  = (const float*)d_in[4];
  const float* ba  = (const float*)d_in[5];
  const float* Wb  = (const float*)d_in[6];
  const float* bb  = (const float*)d_in[7];
  const float* Wg  = (const float*)d_in[8];
  const float* Wo  = (const float*)d_in[9];
  const float* qcw = (const float*)d_in[10];
  const float* qcb = (const float*)d_in[11];
  const float* kcw = (const float*)d_in[12];
  const float* kcb = (const float*)d_in[13];
  const float* vcw = (const float*)d_in[14];
  const float* vcb = (const float*)d_in[15];
  const float* lnw = (const float*)d_in[16];
  const float* lnb = (const float*)d_in[17];
  float* out = (float*)d_out;

  float *qraw, *kraw, *vraw, *graw, *qact, *kact, *vact, *obuf, *alpha, *beta;
  cudaGetSymbolAddress((void**)&qraw, g_qraw);
  cudaGetSymbolAddress((void**)&kraw, g_kraw);
  cudaGetSymbolAddress((void**)&vraw, g_vraw);
  cudaGetSymbolAddress((void**)&graw, g_graw);
  cudaGetSymbolAddress((void**)&qact, g_qact);
  cudaGetSymbolAddress((void**)&kact, g_kact);
  cudaGetSymbolAddress((void**)&vact, g_vact);
  cudaGetSymbolAddress((void**)&obuf, g_obuf);
  cudaGetSymbolAddress((void**)&alpha, g_alpha);
  cudaGetSymbolAddress((void**)&beta, g_beta);

  __nv_bfloat16 *xhi, *xlo, *ghi, *glo;
  __nv_bfloat16 *wqh, *wql, *wkh, *wkl, *wvh, *wvl, *wgh, *wgl, *woh, *wol;
  cudaGetSymbolAddress((void**)&xhi, g_xhi);
  cudaGetSymbolAddress((void**)&xlo, g_xlo);
  cudaGetSymbolAddress((void**)&ghi, g_ghi);
  cudaGetSymbolAddress((void**)&glo, g_glo);
  cudaGetSymbolAddress((void**)&wqh, g_wqhi);
  cudaGetSymbolAddress((void**)&wql, g_wqlo);
  cudaGetSymbolAddress((void**)&wkh, g_wkhi);
  cudaGetSymbolAddress((void**)&wkl, g_wklo);
  cudaGetSymbolAddress((void**)&wvh, g_wvhi);
  cudaGetSymbolAddress((void**)&wvl, g_wvlo);
  cudaGetSymbolAddress((void**)&wgh, g_wghi);
  cudaGetSymbolAddress((void**)&wgl, g_wglo);
  cudaGetSymbolAddress((void**)&woh, g_wohi);
  cudaGetSymbolAddress((void**)&wol, g_wolo);

  cudaFuncSetAttribute(gemm_bf16x3_persist, cudaFuncAttributeMaxDynamicSharedMemorySize, kDynSmem);

  const int n4 = kM * kH / 4;

  // launch 1
  split_rows<<<n4 / 256, 256>>>((const float4*)x, (__nv_bfloat162*)xhi, (__nv_bfloat162*)xlo, n4);
  // launch 2: all 5 weight splits fused
  dim3 tg(kH / 32, kH / 32, 5);
  split_T5<<<tg, 256>>>(Wq, Wk, Wv, Wg, Wo,
                        wqh, wql, wkh, wkl, wvh, wvl, wgh, wgl, woh, wol);
  // launch 3: fused persistent projection GEMM
  gemm_bf16x3_persist<<<kGemmGrid, 256, kDynSmem>>>(
      xhi, xlo,
      wqh, wql, qraw,
      wkh, wkl, kraw,
      wvh, wvl, vraw,
      wgh, wgl, graw,
      4 * kTilesPerGemm);
  // launch 4
  ab_proj<<<kM, 256>>>(x, Wa, ba, Wb, bb, alpha, beta);
  // launch 5
  const int nElem = kM * kH;
  dim3 cg(nElem / 256, 3);
  conv_silu3<<<cg, 256>>>(qraw, kraw, vraw, qcw, qcb, kcw, kcb, vcw, vcb, qact, kact, vact);
  // launch 6 (profiled by ncu -s 5 -c 1)
  recurrence<<<kB * kNH * 4, 128>>>(qact, kact, vact, alpha, beta, obuf);
  // launch 7
  dim3 lg(kM, kNH);
  ln_gate_split<<<lg, 128>>>(obuf, graw, lnw, lnb, ghi, glo);
  // launch 8
  gemm_bf16x3_persist<<<kGemmGrid, 256, kDynSmem>>>(
      ghi, glo,
      woh, wol, out,
      woh, wol, out,
      woh, wol, out,
      woh, wol, out,
      kTilesPerGemm);
}

// round 15
// speedup vs baseline: 1.0399x; 1.0399x over previous
#include <cuda_runtime.h>
#include <cuda_bf16.h>
#include <math.h>
#include <stdint.h>

namespace {
constexpr int kH  = 2048;
constexpr int kNH = 16;
constexpr int kD  = 128;
constexpr int kB  = 2;
constexpr int kS  = 2048;
constexpr int kM  = kB * kS;          // 4096
constexpr int kNumChunks = kH / 64;   // 32
constexpr int kStageBytes = 98304;    // Ahi 16K | Alo 16K | Bhi 32K | Blo 32K
constexpr int kDynSmem = 2 * kStageBytes + 1024;
constexpr int kTilesPerGemm = (kM / 128) * (kH / 256);   // 256
constexpr int kGemmGrid = 148;
constexpr int kRowsPerAB = 4;
}

// ---------------- scratch ----------------
__device__ float g_qraw[(size_t)kM * kH];
__device__ float g_kraw[(size_t)kM * kH];
__device__ float g_vraw[(size_t)kM * kH];
__device__ float g_graw[(size_t)kM * kH];
__device__ float g_qact[(size_t)kM * kH];
__device__ float g_kact[(size_t)kM * kH];
__device__ float g_vact[(size_t)kM * kH];
__device__ float g_obuf[(size_t)kM * kH];
__device__ float g_alpha[(size_t)kM * kNH];
__device__ float g_beta[(size_t)kM * kNH];
__device__ float g_wabt[(size_t)2 * kNH * kH];      // [32][2048] transposed Wa|Wb
__device__ __nv_bfloat16 g_xhi[(size_t)kM * kH];
__device__ __nv_bfloat16 g_xlo[(size_t)kM * kH];
__device__ __nv_bfloat16 g_ghi[(size_t)kM * kH];
__device__ __nv_bfloat16 g_glo[(size_t)kM * kH];
__device__ __nv_bfloat16 g_wqhi[(size_t)kH * kH];
__device__ __nv_bfloat16 g_wqlo[(size_t)kH * kH];
__device__ __nv_bfloat16 g_wkhi[(size_t)kH * kH];
__device__ __nv_bfloat16 g_wklo[(size_t)kH * kH];
__device__ __nv_bfloat16 g_wvhi[(size_t)kH * kH];
__device__ __nv_bfloat16 g_wvlo[(size_t)kH * kH];
__device__ __nv_bfloat16 g_wghi[(size_t)kH * kH];
__device__ __nv_bfloat16 g_wglo[(size_t)kH * kH];
__device__ __nv_bfloat16 g_wohi[(size_t)kH * kH];
__device__ __nv_bfloat16 g_wolo[(size_t)kH * kH];

// ---------------- helpers ----------------
__device__ __forceinline__ uint32_t smem_u32(const void* p) {
  uint32_t a;
  asm("{ .reg .u64 t; cvta.to.shared.u64 t, %1; cvt.u32.u64 %0, t; }" : "=r"(a) : "l"(p));
  return a;
}
__device__ __forceinline__ void cp16(uint32_t dst, const void* src) {
  asm volatile("cp.async.cg.shared.global [%0], [%1], 16;" :: "r"(dst), "l"(src));
}
__device__ __forceinline__ void ldsm_x4(uint32_t* r, uint32_t addr) {
  asm volatile("ldmatrix.sync.aligned.m8n8.x4.shared.b16 {%0,%1,%2,%3}, [%4];"
               : "=r"(r[0]), "=r"(r[1]), "=r"(r[2]), "=r"(r[3]) : "r"(addr));
}
__device__ __forceinline__ void mma_bf16(float* d, const uint32_t* a, const uint32_t* b) {
  asm volatile("mma.sync.aligned.m16n8k16.row.col.f32.bf16.bf16.f32 "
               "{%0,%1,%2,%3}, {%4,%5,%6,%7}, {%8,%9}, {%0,%1,%2,%3};"
               : "+f"(d[0]), "+f"(d[1]), "+f"(d[2]), "+f"(d[3])
               : "r"(a[0]), "r"(a[1]), "r"(a[2]), "r"(a[3]), "r"(b[0]), "r"(b[1]));
}

// ---------------- bf16 split (rows) ----------------
__global__ __launch_bounds__(256) void split_rows(const float4* __restrict__ in,
                                                  __nv_bfloat162* __restrict__ hi,
                                                  __nv_bfloat162* __restrict__ lo,
                                                  int n4) {
  int i = blockIdx.x * 256 + threadIdx.x;
  if (i >= n4) return;
  float4 v = in[i];
  __nv_bfloat162 h01, h23, l01, l23;
  h01.x = __float2bfloat16_rn(v.x);
  h01.y = __float2bfloat16_rn(v.y);
  h23.x = __float2bfloat16_rn(v.z);
  h23.y = __float2bfloat16_rn(v.w);
  l01.x = __float2bfloat16_rn(v.x - __bfloat162float(h01.x));
  l01.y = __float2bfloat16_rn(v.y - __bfloat162float(h01.y));
  l23.x = __float2bfloat16_rn(v.z - __bfloat162float(h23.x));
  l23.y = __float2bfloat16_rn(v.w - __bfloat162float(h23.y));
  hi[2 * i] = h01; hi[2 * i + 1] = h23;
  lo[2 * i] = l01; lo[2 * i + 1] = l23;
}

// ---------------- fused bf16 split + transpose for 5 weights ----------------
__global__ __launch_bounds__(256) void split_T5(const float* __restrict__ W0,
                                                const float* __restrict__ W1,
                                                const float* __restrict__ W2,
                                                const float* __restrict__ W3,
                                                const float* __restrict__ W4,
                                                __nv_bfloat16* __restrict__ T0h, __nv_bfloat16* __restrict__ T0l,
                                                __nv_bfloat16* __restrict__ T1h, __nv_bfloat16* __restrict__ T1l,
                                                __nv_bfloat16* __restrict__ T2h, __nv_bfloat16* __restrict__ T2l,
                                                __nv_bfloat16* __restrict__ T3h, __nv_bfloat16* __restrict__ T3l,
                                                __nv_bfloat16* __restrict__ T4h, __nv_bfloat16* __restrict__ T4l) {
  __shared__ float t[32][33];
  const int z = blockIdx.z;
  const float* W = (z == 0) ? W0 : (z == 1) ? W1 : (z == 2) ? W2 : (z == 3) ? W3 : W4;
  __nv_bfloat16* Thi = (z == 0) ? T0h : (z == 1) ? T1h : (z == 2) ? T2h : (z == 3) ? T3h : T4h;
  __nv_bfloat16* Tlo = (z == 0) ? T0l : (z == 1) ? T1l : (z == 2) ? T2l : (z == 3) ? T3l : T4l;
  const int n0 = blockIdx.x * 32, k0 = blockIdx.y * 32;
  const int tx = threadIdx.x & 31, ty = threadIdx.x >> 5;
#pragma unroll
  for (int r = ty; r < 32; r += 8) t[r][tx] = W[(size_t)(k0 + r) * kH + n0 + tx];
  __syncthreads();
#pragma unroll
  for (int r = ty; r < 32; r += 8) {
    float v = t[tx][r];
    __nv_bfloat16 h = __float2bfloat16_rn(v);
    __nv_bfloat16 l = __float2bfloat16_rn(v - __bfloat162float(h));
    size_t o = (size_t)(n0 + r) * kH + k0 + tx;
    Thi[o] = h;
    Tlo[o] = l;
  }
}

// ---------------- transpose Wa|Wb -> Wab_t[32][2048] ----------------
__global__ __launch_bounds__(256) void ab_transpose(const float* __restrict__ Wa,
                                                    const float* __restrict__ Wb,
                                                    float* __restrict__ Wt) {
  int kk = blockIdx.x * 256 + threadIdx.x;
  if (kk >= kH) return;
#pragma unroll
  for (int g = 0; g < kNH; ++g) {
    Wt[(size_t)g * kH + kk] = Wa[(size_t)kk * kNH + g];
    Wt[(size_t)(kNH + g) * kH + kk] = Wb[(size_t)kk * kNH + g];
  }
}

// ---------------- persistent HMMA bf16x3 GEMM, 128x256 tile, 2-stage -------
__global__ __launch_bounds__(256, 1)
void gemm_bf16x3_persist(const __nv_bfloat16* __restrict__ Ahi,
                         const __nv_bfloat16* __restrict__ Alo,
                         const __nv_bfloat16* __restrict__ B0h, const __nv_bfloat16* __restrict__ B0l, float* __restrict__ C0,
                         const __nv_bfloat16* __restrict__ B1h, const __nv_bfloat16* __restrict__ B1l, float* __restrict__ C1,
                         const __nv_bfloat16* __restrict__ B2h, const __nv_bfloat16* __restrict__ B2l, float* __restrict__ C2,
                         const __nv_bfloat16* __restrict__ B3h, const __nv_bfloat16* __restrict__ B3l, float* __restrict__ C3,
                         int totalTiles) {
  extern __shared__ char dsm[];
  const __nv_bfloat16* Bh[4] = {B0h, B1h, B2h, B3h};
  const __nv_bfloat16* Bl[4] = {B0l, B1l, B2l, B3l};
  float* Cp[4] = {C0, C1, C2, C3};

  const int tid = threadIdx.x;
  const int wid = tid >> 5;
  const int lane = tid & 31;
  const int wm = (wid & 1) * 64;
  const int wn = (wid >> 1) * 64;
  const uint32_t s0 = (smem_u32(dsm) + 1023u) & ~1023u;

  int ltile = blockIdx.x;
  int lck = 0;
  auto load_chunk = [&](int buf) {
    if (ltile < totalTiles) {
      const int w = ltile >> 8;
      const int ll = ltile & 255;
      const int lbm = (ll >> 3) << 7;
      const int lbn = (ll & 7) << 8;
      const uint32_t sb = s0 + buf * kStageBytes;
      {
        const __nv_bfloat16* srcs[2] = {Ahi, Alo};
#pragma unroll
        for (int tA = 0; tA < 2; ++tA) {
          const uint32_t db = sb + tA * 16384;
          const __nv_bfloat16* src = srcs[tA];
#pragma unroll
          for (int r = 0; r < 4; ++r) {
            int g = tid + r * 256;
            int m = g >> 3, j = g & 7;
            uint32_t dst = db + m * 128 + ((j ^ (m & 7)) << 4);
            cp16(dst, src + (size_t)(lbm + m) * kH + lck * 64 + j * 8);
          }
        }
      }
      {
        const __nv_bfloat16* srcs[2] = {Bh[w], Bl[w]};
#pragma unroll
        for (int tB = 0; tB < 2; ++tB) {
          const uint32_t db = sb + 32768 + tB * 32768;
          const __nv_bfloat16* src = srcs[tB];
#pragma unroll
          for (int r = 0; r < 8; ++r) {
            int g = tid + r * 256;
            int m = g >> 3, j = g & 7;
            uint32_t dst = db + m * 128 + ((j ^ (m & 7)) << 4);
            cp16(dst, src + (size_t)(lbn + m) * kH + lck * 64 + j * 8);
          }
        }
      }
    }
    asm volatile("cp.async.commit_group;");
    if (++lck == kNumChunks) { lck = 0; ltile += kGemmGrid; }
  };

  load_chunk(0);
  load_chunk(1);
  int cbuf = 0;

  for (int ctile = blockIdx.x; ctile < totalTiles; ctile += kGemmGrid) {
    const int which = ctile >> 8;
    const int loc = ctile & 255;
    const int bm = (loc >> 3) << 7;
    const int bn = (loc & 7) << 8;

    float acc[4][8][4];
#pragma unroll
    for (int i = 0; i < 4; ++i)
#pragma unroll
      for (int j = 0; j < 8; ++j)
#pragma unroll
        for (int kq = 0; kq < 4; ++kq) acc[i][j][kq] = 0.f;

    for (int ck = 0; ck < kNumChunks; ++ck) {
      asm volatile("cp.async.wait_group 1;" ::: "memory");
      __syncthreads();

      const uint32_t aHi = s0 + cbuf * kStageBytes;
      const uint32_t aLo = aHi + 16384;
      const uint32_t bHi = aHi + 32768;
      const uint32_t bLo = aHi + 65536;

      const int amRow = wm + (lane & 15);
      const int bnRowP = wn + (lane & 7) + ((lane >> 4) & 1) * 8;

#pragma unroll
      for (int ks = 0; ks < 4; ++ks) {
        const int kcA = ks * 2 + (lane >> 4);
        const int kcB = ks * 2 + ((lane >> 3) & 1);
        uint32_t bh[4][4], bl[4][4];
#pragma unroll
        for (int np = 0; np < 4; ++np) {
          int n = bnRowP + np * 16;
          uint32_t off = n * 128 + ((kcB ^ (n & 7)) << 4);
          ldsm_x4(bh[np], bHi + off);
          ldsm_x4(bl[np], bLo + off);
        }
#pragma unroll
        for (int mt = 0; mt < 4; ++mt) {
          uint32_t ah[4], al[4];
          int m = amRow + mt * 16;
          uint32_t off = m * 128 + ((kcA ^ (m & 7)) << 4);
          ldsm_x4(ah, aHi + off);
          ldsm_x4(al, aLo + off);
#pragma unroll
          for (int nt = 0; nt < 8; ++nt) {
            const uint32_t* bhp = &bh[nt >> 1][(nt & 1) * 2];
            const uint32_t* blp = &bl[nt >> 1][(nt & 1) * 2];
            mma_bf16(acc[mt][nt], ah, bhp);
            mma_bf16(acc[mt][nt], ah, blp);
            mma_bf16(acc[mt][nt], al, bhp);
          }
        }
      }
      __syncthreads();
      load_chunk(cbuf);
      cbuf ^= 1;
    }

    float* C = Cp[which];
    const int r0 = lane >> 2;
    const int c0 = (lane & 3) * 2;
#pragma unroll
    for (int mt = 0; mt < 4; ++mt) {
#pragma unroll
      for (int nt = 0; nt < 8; ++nt) {
        float* p0 = C + (size_t)(bm + wm + mt * 16 + r0) * kH + bn + wn + nt * 8 + c0;
        float* p1 = p0 + 8 * kH;
        *(float2*)p0 = make_float2(acc[mt][nt][0], acc[mt][nt][1]);
        *(float2*)p1 = make_float2(acc[mt][nt][2], acc[mt][nt][3]);
      }
    }
  }
}

// ---------------- fused causal depthwise conv (K=4) + SiLU for q,k,v -------
__global__ __launch_bounds__(256) void conv_silu3(const float* __restrict__ qin,
                                                  const float* __restrict__ kin,
                                                  const float* __restrict__ vin,
                                                  const float* __restrict__ qw, const float* __restrict__ qbias,
                                                  const float* __restrict__ kw, const float* __restrict__ kbias,
                                                  const float* __restrict__ vw, const float* __restrict__ vbias,
                                                  float* __restrict__ qout,
                                                  float* __restrict__ kout,
                                                  float* __restrict__ vout) {
  const int which = blockIdx.y;
  const float* in   = (which == 0) ? qin : (which == 1) ? kin : vin;
  const float* w    = (which == 0) ? qw : (which == 1) ? kw : vw;
  const float* bias = (which == 0) ? qbias : (which == 1) ? kbias : vbias;
  float* out        = (which == 0) ? qout : (which == 1) ? kout : vout;
  const float scale = (which == 1) ? 0.08838834764831845f : 1.f;

  int idx = blockIdx.x * 256 + threadIdx.x;
  int c  = idx & (kH - 1);
  int sb = idx >> 11;
  int s  = sb & (kS - 1);
  const float w0 = w[c * 4 + 0], w1 = w[c * 4 + 1], w2 = w[c * 4 + 2], w3 = w[c * 4 + 3];
  const float* p = in + (size_t)sb * kH + c;
  float y = bias[c] + w3 * p[0];
  if (s >= 1) y += w2 * p[-(ptrdiff_t)kH];
  if (s >= 2) y += w1 * p[-(ptrdiff_t)(2 * kH)];
  if (s >= 3) y += w0 * p[-(ptrdiff_t)(3 * kH)];
  float sg = 1.f / (1.f + __expf(-y));
  out[idx] = y * sg * scale;
}

// ---------------- alpha/beta v2: transposed W, 4 rows/block ----------------
// Thread t: g = t>>3 (0..31 selects alpha-head g or beta-head g-16), l = t&7.
// Per-row summation order identical to v1 (kk = l, l+8, ...; shfl 1,2,4).
__global__ __launch_bounds__(256) void ab_proj(const float* __restrict__ x,
                                               const float* __restrict__ Wt,
                                               const float* __restrict__ ba,
                                               const float* __restrict__ bb,
                                               float* __restrict__ alpha,
                                               float* __restrict__ beta) {
  __shared__ float xs[kRowsPerAB][kH];
  const int row0 = blockIdx.x * kRowsPerAB;
  const int t = threadIdx.x;
#pragma unroll
  for (int rr = 0; rr < kRowsPerAB; ++rr) {
    const float* xr = x + (size_t)(row0 + rr) * kH;
#pragma unroll
    for (int i = 0; i < kH / 256; ++i) xs[rr][t + i * 256] = xr[t + i * 256];
  }
  __syncthreads();
  const int g = t >> 3;
  const int l = t & 7;
  const int head = g & 15;
  const float* wrow = Wt + (size_t)g * kH;
  float acc[kRowsPerAB];
#pragma unroll
  for (int rr = 0; rr < kRowsPerAB; ++rr) acc[rr] = 0.f;
  for (int kk = l; kk < kH; kk += 8) {
    float wv = wrow[kk];
#pragma unroll
    for (int rr = 0; rr < kRowsPerAB; ++rr) acc[rr] = fmaf(xs[rr][kk], wv, acc[rr]);
  }
#pragma unroll
  for (int rr = 0; rr < kRowsPerAB; ++rr) {
    acc[rr] += __shfl_xor_sync(0xffffffffu, acc[rr], 1);
    acc[rr] += __shfl_xor_sync(0xffffffffu, acc[rr], 2);
    acc[rr] += __shfl_xor_sync(0xffffffffu, acc[rr], 4);
  }
  if (l == 0) {
    float bias = (g < 16) ? ba[head] : bb[head];
#pragma unroll
    for (int rr = 0; rr < kRowsPerAB; ++rr) {
      float v = 1.f / (1.f + __expf(-(acc[rr] + bias)));
      if (g < 16) alpha[(size_t)(row0 + rr) * kNH + head] = v;
      else        beta [(size_t)(row0 + rr) * kNH + head] = v;
    }
  }
}

// ---------------- delta-rule recurrence: warp-independent (R13 winner) ------
#define CPA4(dst, src) asm volatile("cp.async.ca.shared.global [%0], [%1], 4;" :: "r"(dst), "l"(src))

__global__ __launch_bounds__(128) void recurrence(const float* __restrict__ qb,
                                                  const float* __restrict__ kb,
                                                  const float* __restrict__ vb,
                                                  const float* __restrict__ alpha,
                                                  const float* __restrict__ beta,
                                                  float* __restrict__ ob) {
  __shared__ __align__(16) float s_k[4][4][128];   // [warp][buf][col]
  __shared__ __align__(16) float s_q[4][4][128];
  __shared__ __align__(16) float s_v[4][4][8];
  __shared__ float s_ab[4][4][2];

  const int t = threadIdx.x;
  const int w = t >> 5;
  const int lane = t & 31;
  const int bid = blockIdx.x;
  const int chunk = bid & 3;
  const int bh = bid >> 2;
  const int h = bh & 15;
  const int b = bh >> 4;
  const size_t head_off = (size_t)h * kD;
  const size_t bs_base = (size_t)b * kS;
  const int rowbase = chunk * 32 + w * 8;

  float S[32];
#pragma unroll
  for (int i = 0; i < 32; ++i) S[i] = 0.f;

  const int r = lane >> 2;
  const int qtr = lane & 3;

  auto issue = [&](int s, int buf) {
    size_t off = (bs_base + s) * (size_t)kH + head_off;
    uint32_t a;
    a = (uint32_t)__cvta_generic_to_shared(&s_k[w][buf][lane * 4]);
    cp16(a, kb + off + lane * 4);
    a = (uint32_t)__cvta_generic_to_shared(&s_q[w][buf][lane * 4]);
    cp16(a, qb + off + lane * 4);
    if (lane < 2) {
      a = (uint32_t)__cvta_generic_to_shared(&s_v[w][buf][lane * 4]);
      cp16(a, vb + off + rowbase + lane * 4);
    } else if (lane == 2) {
      a = (uint32_t)__cvta_generic_to_shared(&s_ab[w][buf][0]);
      CPA4(a, alpha + (bs_base + s) * kNH + h);
    } else if (lane == 3) {
      a = (uint32_t)__cvta_generic_to_shared(&s_ab[w][buf][1]);
      CPA4(a, beta + (bs_base + s) * kNH + h);
    }
    asm volatile("cp.async.commit_group;");
  };

  issue(0, 0);
  issue(1, 1);
  issue(2, 2);

  for (int s = 0; s < kS; ++s) {
    int pf = s + 3;
    if (pf > kS - 1) pf = kS - 1;
    issue(pf, (s + 3) & 3);
    asm volatile("cp.async.wait_group 3;");
    __syncwarp();

    const int buf = s & 3;
    const float4* kp = (const float4*)&s_k[w][buf][qtr * 32];
    const float4* qp = (const float4*)&s_q[w][buf][qtr * 32];
    const float a_ = s_ab[w][buf][0];
    const float b_ = s_ab[w][buf][1];
    const float vi = s_v[w][buf][r];

    float4 kr[8];
    float d0 = 0.f, d1 = 0.f, d2 = 0.f, d3 = 0.f;
#pragma unroll
    for (int m = 0; m < 8; ++m) {
      kr[m] = kp[m];
      d0 = fmaf(S[4 * m + 0], kr[m].x, d0);
      d1 = fmaf(S[4 * m + 1], kr[m].y, d1);
      d2 = fmaf(S[4 * m + 2], kr[m].z, d2);
      d3 = fmaf(S[4 * m + 3], kr[m].w, d3);
    }
    float sk = (d0 + d1) + (d2 + d3);
    sk += __shfl_xor_sync(0xffffffffu, sk, 1);
    sk += __shfl_xor_sync(0xffffffffu, sk, 2);
    const float c = -b_ * (sk - vi);

    float o0 = 0.f, o1 = 0.f, o2 = 0.f, o3 = 0.f;
#pragma unroll
    for (int m = 0; m < 8; ++m) {
      float4 qv = qp[m];
      S[4 * m + 0] = fmaf(c, kr[m].x, a_ * S[4 * m + 0]);
      S[4 * m + 1] = fmaf(c, kr[m].y, a_ * S[4 * m + 1]);
      S[4 * m + 2] = fmaf(c, kr[m].z, a_ * S[4 * m + 2]);
      S[4 * m + 3] = fmaf(c, kr[m].w, a_ * S[4 * m + 3]);
      o0 = fmaf(S[4 * m + 0], qv.x, o0);
      o1 = fmaf(S[4 * m + 1], qv.y, o1);
      o2 = fmaf(S[4 * m + 2], qv.z, o2);
      o3 = fmaf(S[4 * m + 3], qv.w, o3);
    }
    float oo = (o0 + o1) + (o2 + o3);
    oo += __shfl_xor_sync(0xffffffffu, oo, 1);
    oo += __shfl_xor_sync(0xffffffffu, oo, 2);
    if (qtr == 0) {
      ob[(bs_base + s) * (size_t)kH + head_off + rowbase + r] = oo;
    }
    __syncwarp();
  }
}

// ---------------- LayerNorm + gate + bf16 split (fused) ---------------------
__global__ __launch_bounds__(128) void ln_gate_split(const float* __restrict__ ob,
                                                     const float* __restrict__ graw,
                                                     const float* __restrict__ lnw,
                                                     const float* __restrict__ lnb,
                                                     __nv_bfloat16* __restrict__ ghi,
                                                     __nv_bfloat16* __restrict__ glo) {
  __shared__ float red[8];
  const int bs = blockIdx.x;
  const int h = blockIdx.y;
  const int t = threadIdx.x;
  size_t idx = (size_t)bs * kH + (size_t)h * kD + t;
  float v = ob[idx];
  float s1 = v, s2 = v * v;
#pragma unroll
  for (int w = 16; w; w >>= 1) {
    s1 += __shfl_xor_sync(0xffffffffu, s1, w);
    s2 += __shfl_xor_sync(0xffffffffu, s2, w);
  }
  const int wid = t >> 5, lane = t & 31;
  if (lane == 0) { red[wid] = s1; red[4 + wid] = s2; }
  __syncthreads();
  if (t == 0) {
    red[0] = red[0] + red[1] + red[2] + red[3];
    red[4] = red[4] + red[5] + red[6] + red[7];
  }
  __syncthreads();
  float mean = red[0] * (1.f / 128.f);
  float var = red[4] * (1.f / 128.f) - mean * mean;
  float rs = rsqrtf(var + 1e-5f);
  float y = (v - mean) * rs * lnw[t] + lnb[t];
  float gv = graw[idx];
  float o = y * (1.f / (1.f + __expf(-gv)));
  __nv_bfloat16 hi = __float2bfloat16_rn(o);
  __nv_bfloat16 lo = __float2bfloat16_rn(o - __bfloat162float(hi));
  ghi[idx] = hi;
  glo[idx] = lo;
}

// ---------------- launcher ----------------
extern "C" void kernel_launch(void* const* d_in, const int* in_sizes, int n_in,
                              void* d_out, int out_size) {
  const float* x   = (const float*)d_in[0];
  const float* Wq  = (const float*)d_in[1];
  const float* Wk  = (const float*)d_in[2];
  const float* Wv  = (const float*)d_in[3];
  const float* Wa  = (const float*)d_in[4];
  const float* ba  = (const float*)d_in[5];
  const float* Wb  = (const float*)d_in[6];
  const float* bb  = (const float*)d_in[7];
  const float* Wg  = (const float*)d_in[8];
  const float* Wo  = (const float*)d_in[9];
  const float* qcw = (const float*)d_in[10];
  const float* qcb = (const float*)d_in[11];
  const float* kcw = (const float*)d_in[12];
  const float* kcb = (const float*)d_in[13];
  const float* vcw = (const float*)d_in[14];
  const float* vcb = (const float*)d_in[15];
  const float* lnw = (const float*)d_in[16];
  const float* lnb = (const float*)d_in[17];
  float* out = (float*)d_out;

  float *qraw, *kraw, *vraw, *graw, *qact, *kact, *vact, *obuf, *alpha, *beta, *wabt;
  cudaGetSymbolAddress((void**)&qraw, g_qraw);
  cudaGetSymbolAddress((void**)&kraw, g_kraw);
  cudaGetSymbolAddress((void**)&vraw, g_vraw);
  cudaGetSymbolAddress((void**)&graw, g_graw);
  cudaGetSymbolAddress((void**)&qact, g_qact);
  cudaGetSymbolAddress((void**)&kact, g_kact);
  cudaGetSymbolAddress((void**)&vact, g_vact);
  cudaGetSymbolAddress((void**)&obuf, g_obuf);
  cudaGetSymbolAddress((void**)&alpha, g_alpha);
  cudaGetSymbolAddress((void**)&beta, g_beta);
  cudaGetSymbolAddress((void**)&wabt, g_wabt);

  __nv_bfloat16 *xhi, *xlo, *ghi, *glo;
  __nv_bfloat16 *wqh, *wql, *wkh, *wkl, *wvh, *wvl, *wgh, *wgl, *woh, *wol;
  cudaGetSymbolAddress((void**)&xhi, g_xhi);
  cudaGetSymbolAddress((void**)&xlo, g_xlo);
  cudaGetSymbolAddress((void**)&ghi, g_ghi);
  cudaGetSymbolAddress((void**)&glo, g_glo);
  cudaGetSymbolAddress((void**)&wqh, g_wqhi);
  cudaGetSymbolAddress((void**)&wql, g_wqlo);
  cudaGetSymbolAddress((void**)&wkh, g_wkhi);
  cudaGetSymbolAddress((void**)&wkl, g_wklo);
  cudaGetSymbolAddress((void**)&wvh, g_wvhi);
  cudaGetSymbolAddress((void**)&wvl, g_wvlo);
  cudaGetSymbolAddress((void**)&wgh, g_wghi);
  cudaGetSymbolAddress((void**)&wgl, g_wglo);
  cudaGetSymbolAddress((void**)&woh, g_wohi);
  cudaGetSymbolAddress((void**)&wol, g_wolo);

  cudaFuncSetAttribute(gemm_bf16x3_persist, cudaFuncAttributeMaxDynamicSharedMemorySize, kDynSmem);

  const int n4 = kM * kH / 4;

  split_rows<<<n4 / 256, 256>>>((const float4*)x, (__nv_bfloat162*)xhi, (__nv_bfloat162*)xlo, n4);
  dim3 tg(kH / 32, kH / 32, 5);
  split_T5<<<tg, 256>>>(Wq, Wk, Wv, Wg, Wo,
                        wqh, wql, wkh, wkl, wvh, wvl, wgh, wgl, woh, wol);
  ab_transpose<<<kH / 256, 256>>>(Wa, Wb, wabt);
  gemm_bf16x3_persist<<<kGemmGrid, 256, kDynSmem>>>(
      xhi, xlo,
      wqh, wql, qraw,
      wkh, wkl, kraw,
      wvh, wvl, vraw,
      wgh, wgl, graw,
      4 * kTilesPerGemm);
  ab_proj<<<kM / kRowsPerAB, 256>>>(x, wabt, ba, bb, alpha, beta);
  const int nElem = kM * kH;
  dim3 cg(nElem / 256, 3);
  conv_silu3<<<cg, 256>>>(qraw, kraw, vraw, qcw, qcb, kcw, kcb, vcw, vcb, qact, kact, vact);
  recurrence<<<kB * kNH * 4, 128>>>(qact, kact, vact, alpha, beta, obuf);
  dim3 lg(kM, kNH);
  ln_gate_split<<<lg, 128>>>(obuf, graw, lnw, lnb, ghi, glo);
  gemm_bf16x3_persist<<<kGemmGrid, 256, kDynSmem>>>(
      ghi, glo,
      woh, wol, out,
      woh, wol, out,
      woh, wol, out,
      woh, wol, out,
      kTilesPerGemm);
}